// round 14
// baseline (speedup 1.0000x reference)
#include <cuda_runtime.h>
#include <math.h>

#define FATOL 1e-8f
#define FRTOL 1e-5f
#define EP3   0.0003f      /* 3 * EP, EP = 1e-4 */
#define EPMAX2 900.0f      /* EPMAX^2 */

#define MAX_L 2048
#define MAX_P 131072
#define NT_MAIN 256
#define NSLOT 3                       /* 2 points per slot -> 6 points/thread */
#define PTS_PER_GROUP (NT_MAIN * 2 * NSLOT)   /* 1536 */
#define NSTRIPE 222                   /* frame segments; grid = npg*222 */
#define TS 48                         /* smem frame tile */

typedef unsigned long long u64;
typedef ulonglong2 U2;

#define FMA2(d,a,b,c) asm("fma.rn.f32x2 %0, %1, %2, %3;" : "=l"(d) : "l"(a), "l"(b), "l"(c))
#define PACK2(d,lo,hi) asm("mov.b64 %0, {%1, %2};" : "=l"(d) : "f"(lo), "f"(hi))
#define UNPK2(lo,hi,s) asm("mov.b64 {%0, %1}, %2;" : "=f"(lo), "=f"(hi) : "l"(s))

struct Ctl { int pair_count; int done; double sum; };
__device__ Ctl  g_ctl;                /* zero-init; self-reset by main kernel */
__device__ int2 g_pairs[MAX_P];

__device__ __forceinline__ u64 dupf(float v) { u64 r; PACK2(r, v, v); return r; }

/* --------------- rigid_from_3 of one target residue ----------------- */
__device__ __forceinline__ void rigid3_dev(const float* __restrict__ x,
                                           float* R, float* O) {
    float x1x = x[0], x1y = x[1], x1z = x[2];
    float x2x = x[3], x2y = x[4], x2z = x[5];
    float x3x = x[6], x3y = x[7], x3z = x[8];
    float v1x = x3x - x2x, v1y = x3y - x2y, v1z = x3z - x2z;
    float v2x = x1x - x2x, v2y = x1y - x2y, v2z = x1z - x2z;
    float n1 = sqrtf(v1x*v1x + v1y*v1y + v1z*v1z) + 0.001f;
    float e1x = v1x/n1, e1y = v1y/n1, e1z = v1z/n1;
    float dp = e1x*v2x + e1y*v2y + e1z*v2z;
    float u2x = v2x - e1x*dp, u2y = v2y - e1y*dp, u2z = v2z - e1z*dp;
    float n2 = sqrtf(u2x*u2x + u2y*u2y + u2z*u2z) + 1e-8f;
    float e2x = u2x/n2, e2y = u2y/n2, e2z = u2z/n2;
    R[0]=e1x; R[1]=e1y; R[2]=e1z;
    R[3]=e2x; R[4]=e2y; R[5]=e2z;
    R[6]=e1y*e2z - e1z*e2y;
    R[7]=e1z*e2x - e1x*e2z;
    R[8]=e1x*e2y - e1y*e2x;
    O[0]=x2x; O[1]=x2y; O[2]=x2z;
}

/* ---------------- merge math ---------------------------------------- */
__device__ __forceinline__ void merge_frames_dev(
    const float* RA, const float* OA, const float* RB, const float* OB,
    float* R, float* O)
{
    bool close = (fabsf(OA[0]-OB[0]) <= FATOL + FRTOL*fabsf(OB[0]))
              && (fabsf(OA[1]-OB[1]) <= FATOL + FRTOL*fabsf(OB[1]))
              && (fabsf(OA[2]-OB[2]) <= FATOL + FRTOL*fabsf(OB[2]));
    float d0 = OB[0]-OA[0], d1 = OB[1]-OA[1], d2 = OB[2]-OA[2];
    float nd = sqrtf(d0*d0 + d1*d1 + d2*d2);
    float snd = (nd == 0.f) ? 1.f : nd;
    float X0 = d0/snd, X1 = d1/snd, X2 = d2/snd;
    float Za0 = RA[6]+RB[6], Za1 = RA[7]+RB[7], Za2 = RA[8]+RB[8];
    float Zs0 = RA[6]-RB[6], Zs1 = RA[7]-RB[7], Zs2 = RA[8]-RB[8];
    float na = sqrtf(Za0*Za0 + Za1*Za1 + Za2*Za2);
    float ns = sqrtf(Zs0*Zs0 + Zs1*Zs1 + Zs2*Zs2);
    float Z0, Z1, Z2;
    if (na > ns) { float s = (na == 0.f) ? 1.f : na; Z0 = Za0/s; Z1 = Za1/s; Z2 = Za2/s; }
    else         { float s = (ns == 0.f) ? 1.f : ns; Z0 = Zs0/s; Z1 = Zs1/s; Z2 = Zs2/s; }
    float Y0 = Z1*X2 - Z2*X1;
    float Y1 = Z2*X0 - Z0*X2;
    float Y2 = Z0*X1 - Z1*X0;
    bool nanbad = isnan(Y0) || isnan(Y1) || isnan(Y2);
    float C0 = X1*Y2 - X2*Y1;
    float C1 = X2*Y0 - X0*Y2;
    float C2 = X0*Y1 - X1*Y0;
    if (C0*Z0 + C1*Z1 + C2*Z2 < 0.f) { Y0 = -Y0; Y1 = -Y1; Y2 = -Y2; }
    bool bad = close || (nd == 0.f) || (na == 0.f) || (ns == 0.f) || nanbad;
    if (bad) {
#pragma unroll
        for (int k = 0; k < 9; k++) R[k] = RA[k];
        O[0] = OA[0]; O[1] = OA[1]; O[2] = OA[2];
    } else {
        R[0] = X0; R[1] = X1; R[2] = X2;
        R[3] = Y0; R[4] = Y1; R[5] = Y2;
        R[6] = Z0; R[7] = Z1; R[8] = Z2;
        O[0] = 0.5f*(OA[0]+OB[0]); O[1] = 0.5f*(OA[1]+OB[1]); O[2] = 0.5f*(OA[2]+OB[2]);
    }
}

/* ---------------- prep: pure pair compaction (proven config) -------- */
__global__ void pairs_kernel_vec4(const int* __restrict__ m, int L) {
    int i  = blockIdx.x;
    int j4 = (blockIdx.y * blockDim.x + threadIdx.x) * 4;
    int cnt = 0; int js[4];
    if (j4 < L) {
        int4 v = *(const int4*)(m + (long)i * L + j4);
        int vv[4] = {v.x, v.y, v.z, v.w};
#pragma unroll
        for (int u = 0; u < 4; u++) {
            int j = j4 + u;
            if (j < L && j > i && vv[u] == 1) js[cnt++] = j;
        }
    }
    int lane = threadIdx.x & 31;
    int scan = cnt;
#pragma unroll
    for (int off = 1; off < 32; off <<= 1) {
        int n = __shfl_up_sync(0xffffffffu, scan, off);
        if (lane >= off) scan += n;
    }
    int total = __shfl_sync(0xffffffffu, scan, 31);
    int base = 0;
    if (lane == 31 && total) base = atomicAdd(&g_ctl.pair_count, total);
    base = __shfl_sync(0xffffffffu, base, 31);
    int pos = base + scan - cnt;
    for (int u = 0; u < cnt; u++)
        if (pos + u < MAX_P) g_pairs[pos + u] = make_int2(i, js[u]);
}

__global__ void pairs_kernel_scalar(const int* __restrict__ m, int L) {
    int i = blockIdx.x;
    int j = blockIdx.y * blockDim.x + threadIdx.x;
    bool pred = (j < L) && (j > i) && (m[(long)i * L + j] == 1);
    unsigned bal = __ballot_sync(0xffffffffu, pred);
    int cnt = __popc(bal);
    int lane = threadIdx.x & 31;
    int base = 0;
    if (lane == 0 && cnt) base = atomicAdd(&g_ctl.pair_count, cnt);
    base = __shfl_sync(0xffffffffu, base, 0);
    if (pred) {
        int r = base + __popc(bal & ((1u << lane) - 1u));
        if (r < MAX_P) g_pairs[r] = make_int2(i, j);
    }
}

/* --------------- main: in-block records + prefetched fma loop ------- */
template<bool FULL>
__global__ void __launch_bounds__(NT_MAIN, 3)
fape_main_kernel(const float* __restrict__ coor, const float* __restrict__ target,
                 const float* __restrict__ rot, const float* __restrict__ trans,
                 int L, int npg, float* __restrict__ out) {
    const int npts = 3 * L;
    const int t = threadIdx.x;
    const int pg     = blockIdx.x % npg;       /* point group */
    const int stripe = blockIdx.x / npg;       /* frame segment index */
    const int pbase  = pg * PTS_PER_GROUP;

    __shared__ U2 s_fr[TS * 12];
    __shared__ float wsum[NT_MAIN / 32];

    const int F = L + min(g_ctl.pair_count, MAX_P);
    const int seg = (F + NSTRIPE - 1) / NSTRIPE;     /* frames per block segment */
    const int f0 = stripe * seg;
    const int f1 = min(f0 + seg, F);

    /* ---- build first tile's records FIRST (overlaps point LDGs) ---- */
    int tile_base = f0;
    {
        int nf = min(TS, f1 - tile_base);
        if (t < nf) {
            int fidx = tile_base + t;
            float Rp[9], tp[3], Rt[9], tq[3];
            if (fidx < L) {
#pragma unroll
                for (int k = 0; k < 9; k++) Rp[k] = rot[(long)fidx*9 + k];
                tp[0] = trans[fidx*3+0]; tp[1] = trans[fidx*3+1]; tp[2] = trans[fidx*3+2];
                rigid3_dev(target + (long)fidx*9, Rt, tq);
            } else {
                int2 pr = g_pairs[fidx - L];
                int i = pr.x, j = pr.y;
                merge_frames_dev(rot + (long)9*i, trans + (long)3*i,
                                 rot + (long)9*j, trans + (long)3*j, Rp, tp);
                float RA[9], OA[3], RB[9], OB[3];
                rigid3_dev(target + (long)9*i, RA, OA);
                rigid3_dev(target + (long)9*j, RB, OB);
                merge_frames_dev(RA, OA, RB, OB, Rt, tq);
            }
            U2* o = s_fr + t * 12;
#pragma unroll
            for (int e = 0; e < 3; e++) {
                float c = (Rt[3*e+0]*tq[0] + Rt[3*e+1]*tq[1] + Rt[3*e+2]*tq[2])
                        - (Rp[3*e+0]*tp[0] + Rp[3*e+1]*tp[1] + Rp[3*e+2]*tp[2]);
                U2 m0, m1, m2, m3;
                m0.x = dupf(Rp[3*e+0]);  m0.y = dupf(Rp[3*e+1]);
                m1.x = dupf(Rp[3*e+2]);  m1.y = dupf(c);
                m2.x = dupf(-Rt[3*e+0]); m2.y = dupf(-Rt[3*e+1]);
                m3.x = dupf(-Rt[3*e+2]); m3.y = 0ull;
                o[4*e+0] = m0; o[4*e+1] = m1; o[4*e+2] = m2; o[4*e+3] = m3;
            }
        }
    }

    /* ---- per-thread points in registers (packed pairs) ---- */
    u64 Px[NSLOT], Py[NSLOT], Pz[NSLOT], Qx[NSLOT], Qy[NSLOT], Qz[NSLOT];
    float M0[NSLOT], M1[NSLOT];
#pragma unroll
    for (int k = 0; k < NSLOT; k++) {
        int n0 = pbase + t + (2*k)   * NT_MAIN;
        int n1 = pbase + t + (2*k+1) * NT_MAIN;
        int a0 = (FULL || n0 < npts) ? n0 : 0;
        int a1 = (FULL || n1 < npts) ? n1 : 0;
        float p0x = coor[3*a0],   p0y = coor[3*a0+1],   p0z = coor[3*a0+2];
        float p1x = coor[3*a1],   p1y = coor[3*a1+1],   p1z = coor[3*a1+2];
        float q0x = target[3*a0], q0y = target[3*a0+1], q0z = target[3*a0+2];
        float q1x = target[3*a1], q1y = target[3*a1+1], q1z = target[3*a1+2];
        PACK2(Px[k], p0x, p1x); PACK2(Py[k], p0y, p1y); PACK2(Pz[k], p0z, p1z);
        PACK2(Qx[k], q0x, q1x); PACK2(Qy[k], q0y, q1y); PACK2(Qz[k], q0z, q1z);
        if (!FULL) {
            M0[k] = (n0 < npts) ? 1.f : 0.f;
            M1[k] = (n1 < npts) ? 1.f : 0.f;
        }
    }

    u64 EPp; PACK2(EPp, EP3, EP3);
    float acc0 = 0.f, acc1 = 0.f;

    /* load one row (4 x U2) of frame data from smem */
    auto ld_row = [&](int idx, U2* m) {
        m[0] = s_fr[idx+0]; m[1] = s_fr[idx+1];
        m[2] = s_fr[idx+2]; m[3] = s_fr[idx+3];
    };

    /* compute ss[3] for frame lf; cur holds row0 of lf on entry and
       row0 of nxt0_idx (prefetched) on exit */
    auto compute_ss = [&](int lf, int nxt0_idx, u64* ss, U2* cur) {
#pragma unroll
        for (int e = 0; e < 3; e++) {
            U2 nxt[4];
            int ni = (e < 2) ? (lf * 12 + 4 * (e + 1)) : nxt0_idx;
            ld_row(ni, nxt);                 /* prefetch hides under FMA2s */
            u64 R0 = cur[0].x, R1 = cur[0].y, R2 = cur[1].x, Ce = cur[1].y;
            u64 S0 = cur[2].x, S1 = cur[2].y, S2 = cur[3].x;
#pragma unroll
            for (int k = 0; k < NSLOT; k++) {
                u64 d;
                FMA2(d, S2, Qz[k], Ce); FMA2(d, S1, Qy[k], d); FMA2(d, S0, Qx[k], d);
                FMA2(d, R2, Pz[k], d);  FMA2(d, R1, Py[k], d); FMA2(d, R0, Px[k], d);
                if (e == 0) { FMA2(ss[k], d, d, EPp); }
                else        { FMA2(ss[k], d, d, ss[k]); }
            }
            cur[0] = nxt[0]; cur[1] = nxt[1]; cur[2] = nxt[2]; cur[3] = nxt[3];
        }
    };
    auto tail = [&](const u64* ss) {
#pragma unroll
        for (int k = 0; k < NSLOT; k++) {
            float s0, s1; UNPK2(s0, s1, ss[k]);
            s0 = fminf(s0, EPMAX2);  s1 = fminf(s1, EPMAX2);
            float r0, r1;
            asm("sqrt.approx.f32 %0, %1;" : "=f"(r0) : "f"(s0));
            asm("sqrt.approx.f32 %0, %1;" : "=f"(r1) : "f"(s1));
            if (FULL) { acc0 += r0; acc1 += r1; }
            else      { acc0 = fmaf(M0[k], r0, acc0); acc1 = fmaf(M1[k], r1, acc1); }
        }
    };

    while (tile_base < f1) {
        int nf = min(TS, f1 - tile_base);
        __syncthreads();   /* records for this tile ready */

        U2 cur[4];
        ld_row(0, cur);    /* frame 0, row 0 */
        u64 ssA[NSLOT], ssB[NSLOT];
        /* nxt0 of frame lf = row0 of lf+1 (or 0, harmless re-read) */
        compute_ss(0, (1 < nf) ? 12 : 0, ssA, cur);
        int lf = 1;
        for (; lf + 1 < nf; lf += 2) {
            compute_ss(lf, (lf + 1) * 12, ssB, cur);
            tail(ssA);
            compute_ss(lf + 1, (lf + 2 < nf) ? (lf + 2) * 12 : 0, ssA, cur);
            tail(ssB);
        }
        if (lf < nf) {
            compute_ss(lf, 0, ssB, cur);
            tail(ssA);
            tail(ssB);
        } else {
            tail(ssA);
        }

        tile_base += TS;
        if (tile_base < f1) {
            __syncthreads();
            int nf2 = min(TS, f1 - tile_base);
            if (t < nf2) {
                int fidx = tile_base + t;
                float Rp[9], tp[3], Rt[9], tq[3];
                if (fidx < L) {
#pragma unroll
                    for (int k = 0; k < 9; k++) Rp[k] = rot[(long)fidx*9 + k];
                    tp[0] = trans[fidx*3+0]; tp[1] = trans[fidx*3+1]; tp[2] = trans[fidx*3+2];
                    rigid3_dev(target + (long)fidx*9, Rt, tq);
                } else {
                    int2 pr = g_pairs[fidx - L];
                    int i = pr.x, j = pr.y;
                    merge_frames_dev(rot + (long)9*i, trans + (long)3*i,
                                     rot + (long)9*j, trans + (long)3*j, Rp, tp);
                    float RA[9], OA[3], RB[9], OB[3];
                    rigid3_dev(target + (long)9*i, RA, OA);
                    rigid3_dev(target + (long)9*j, RB, OB);
                    merge_frames_dev(RA, OA, RB, OB, Rt, tq);
                }
                U2* o = s_fr + t * 12;
#pragma unroll
                for (int e = 0; e < 3; e++) {
                    float c = (Rt[3*e+0]*tq[0] + Rt[3*e+1]*tq[1] + Rt[3*e+2]*tq[2])
                            - (Rp[3*e+0]*tp[0] + Rp[3*e+1]*tp[1] + Rp[3*e+2]*tp[2]);
                    U2 m0, m1, m2, m3;
                    m0.x = dupf(Rp[3*e+0]);  m0.y = dupf(Rp[3*e+1]);
                    m1.x = dupf(Rp[3*e+2]);  m1.y = dupf(c);
                    m2.x = dupf(-Rt[3*e+0]); m2.y = dupf(-Rt[3*e+1]);
                    m3.x = dupf(-Rt[3*e+2]); m3.y = 0ull;
                    o[4*e+0] = m0; o[4*e+1] = m1; o[4*e+2] = m2; o[4*e+3] = m3;
                }
            }
        }
    }

    /* block reduction -> one double atomic, last block finalizes + resets */
    float acc = acc0 + acc1;
#pragma unroll
    for (int off = 16; off; off >>= 1)
        acc += __shfl_down_sync(0xffffffffu, acc, off);
    if ((t & 31) == 0) wsum[t >> 5] = acc;
    __syncthreads();
    if (t == 0) {
        float v = 0.f;
#pragma unroll
        for (int w = 0; w < NT_MAIN / 32; w++) v += wsum[w];
        atomicAdd(&g_ctl.sum, (double)v);
        __threadfence();
        int d = atomicAdd(&g_ctl.done, 1);
        if (d == (int)gridDim.x - 1) {
            double s = atomicAdd(&g_ctl.sum, 0.0);
            out[0] = (float)(s / ((double)npts * (double)F));
            /* self-reset for next graph replay */
            g_ctl.pair_count = 0;
            g_ctl.sum = 0.0;
            __threadfence();
            g_ctl.done = 0;
        }
    }
}

/* ------------------------------------------------------------------ */
extern "C" void kernel_launch(void* const* d_in, const int* in_sizes, int n_in,
                              void* d_out, int out_size) {
    const float* coor   = (const float*)d_in[0];
    const float* rot    = (const float*)d_in[1];
    const float* trans  = (const float*)d_in[2];
    const float* target = (const float*)d_in[3];
    const int*   matrix = (const int*)d_in[4];
    int L = in_sizes[0] / 9;
    int npts = 3 * L;

    if ((L & 3) == 0) {
        dim3 pg(L, (L/4 + 255) / 256);
        pairs_kernel_vec4<<<pg, 256>>>(matrix, L);
    } else {
        dim3 pg(L, (L + 255) / 256);
        pairs_kernel_scalar<<<pg, 256>>>(matrix, L);
    }

    int npg = (npts + PTS_PER_GROUP - 1) / PTS_PER_GROUP;
    if (npg < 1) npg = 1;
    dim3 grid(npg * NSTRIPE);

    if (npts % PTS_PER_GROUP == 0)
        fape_main_kernel<true ><<<grid, NT_MAIN>>>(coor, target, rot, trans, L, npg, (float*)d_out);
    else
        fape_main_kernel<false><<<grid, NT_MAIN>>>(coor, target, rot, trans, L, npg, (float*)d_out);
}

// round 15
// speedup vs baseline: 1.0617x; 1.0617x over previous
#include <cuda_runtime.h>
#include <math.h>

#define FATOL 1e-8f
#define FRTOL 1e-5f
#define EP3   0.0003f      /* 3 * EP, EP = 1e-4 */
#define EPMAX2 900.0f      /* EPMAX^2 */

#define MAX_L 2048
#define MAX_P 131072
#define NT_MAIN 256
#define NSLOT 3                       /* 2 points per slot -> 6 points/thread */
#define PTS_PER_GROUP (NT_MAIN * 2 * NSLOT)   /* 1536 */
#define NSTRIPE 222                   /* frame segments; grid = npg*222 */
#define TS 48                         /* smem frame tile */

typedef unsigned long long u64;

#define FMA2(d,a,b,c) asm("fma.rn.f32x2 %0, %1, %2, %3;" : "=l"(d) : "l"(a), "l"(b), "l"(c))
#define PACK2(d,lo,hi) asm("mov.b64 %0, {%1, %2};" : "=l"(d) : "f"(lo), "f"(hi))
#define UNPK2(lo,hi,s) asm("mov.b64 {%0, %1}, %2;" : "=f"(lo), "=f"(hi) : "l"(s))

struct Ctl { int pair_count; int done; double sum; };
__device__ Ctl  g_ctl;                /* zero-init; self-reset by main kernel */
__device__ int2 g_pairs[MAX_P];

__device__ __forceinline__ u64 dupf(float v) { u64 r; PACK2(r, v, v); return r; }

/* --------------- rigid_from_3 of one target residue ----------------- */
__device__ __forceinline__ void rigid3_dev(const float* __restrict__ x,
                                           float* R, float* O) {
    float x1x = x[0], x1y = x[1], x1z = x[2];
    float x2x = x[3], x2y = x[4], x2z = x[5];
    float x3x = x[6], x3y = x[7], x3z = x[8];
    float v1x = x3x - x2x, v1y = x3y - x2y, v1z = x3z - x2z;
    float v2x = x1x - x2x, v2y = x1y - x2y, v2z = x1z - x2z;
    float n1 = sqrtf(v1x*v1x + v1y*v1y + v1z*v1z) + 0.001f;
    float e1x = v1x/n1, e1y = v1y/n1, e1z = v1z/n1;
    float dp = e1x*v2x + e1y*v2y + e1z*v2z;
    float u2x = v2x - e1x*dp, u2y = v2y - e1y*dp, u2z = v2z - e1z*dp;
    float n2 = sqrtf(u2x*u2x + u2y*u2y + u2z*u2z) + 1e-8f;
    float e2x = u2x/n2, e2y = u2y/n2, e2z = u2z/n2;
    R[0]=e1x; R[1]=e1y; R[2]=e1z;
    R[3]=e2x; R[4]=e2y; R[5]=e2z;
    R[6]=e1y*e2z - e1z*e2y;
    R[7]=e1z*e2x - e1x*e2z;
    R[8]=e1x*e2y - e1y*e2x;
    O[0]=x2x; O[1]=x2y; O[2]=x2z;
}

/* ---------------- merge math ---------------------------------------- */
__device__ __forceinline__ void merge_frames_dev(
    const float* RA, const float* OA, const float* RB, const float* OB,
    float* R, float* O)
{
    bool close = (fabsf(OA[0]-OB[0]) <= FATOL + FRTOL*fabsf(OB[0]))
              && (fabsf(OA[1]-OB[1]) <= FATOL + FRTOL*fabsf(OB[1]))
              && (fabsf(OA[2]-OB[2]) <= FATOL + FRTOL*fabsf(OB[2]));
    float d0 = OB[0]-OA[0], d1 = OB[1]-OA[1], d2 = OB[2]-OA[2];
    float nd = sqrtf(d0*d0 + d1*d1 + d2*d2);
    float snd = (nd == 0.f) ? 1.f : nd;
    float X0 = d0/snd, X1 = d1/snd, X2 = d2/snd;
    float Za0 = RA[6]+RB[6], Za1 = RA[7]+RB[7], Za2 = RA[8]+RB[8];
    float Zs0 = RA[6]-RB[6], Zs1 = RA[7]-RB[7], Zs2 = RA[8]-RB[8];
    float na = sqrtf(Za0*Za0 + Za1*Za1 + Za2*Za2);
    float ns = sqrtf(Zs0*Zs0 + Zs1*Zs1 + Zs2*Zs2);
    float Z0, Z1, Z2;
    if (na > ns) { float s = (na == 0.f) ? 1.f : na; Z0 = Za0/s; Z1 = Za1/s; Z2 = Za2/s; }
    else         { float s = (ns == 0.f) ? 1.f : ns; Z0 = Zs0/s; Z1 = Zs1/s; Z2 = Zs2/s; }
    float Y0 = Z1*X2 - Z2*X1;
    float Y1 = Z2*X0 - Z0*X2;
    float Y2 = Z0*X1 - Z1*X0;
    bool nanbad = isnan(Y0) || isnan(Y1) || isnan(Y2);
    float C0 = X1*Y2 - X2*Y1;
    float C1 = X2*Y0 - X0*Y2;
    float C2 = X0*Y1 - X1*Y0;
    if (C0*Z0 + C1*Z1 + C2*Z2 < 0.f) { Y0 = -Y0; Y1 = -Y1; Y2 = -Y2; }
    bool bad = close || (nd == 0.f) || (na == 0.f) || (ns == 0.f) || nanbad;
    if (bad) {
#pragma unroll
        for (int k = 0; k < 9; k++) R[k] = RA[k];
        O[0] = OA[0]; O[1] = OA[1]; O[2] = OA[2];
    } else {
        R[0] = X0; R[1] = X1; R[2] = X2;
        R[3] = Y0; R[4] = Y1; R[5] = Y2;
        R[6] = Z0; R[7] = Z1; R[8] = Z2;
        O[0] = 0.5f*(OA[0]+OB[0]); O[1] = 0.5f*(OA[1]+OB[1]); O[2] = 0.5f*(OA[2]+OB[2]);
    }
}

/* ---------------- prep: pure pair compaction (proven config) -------- */
__global__ void pairs_kernel_vec4(const int* __restrict__ m, int L) {
    int i  = blockIdx.x;
    int j4 = (blockIdx.y * blockDim.x + threadIdx.x) * 4;
    int cnt = 0; int js[4];
    if (j4 < L) {
        int4 v = *(const int4*)(m + (long)i * L + j4);
        int vv[4] = {v.x, v.y, v.z, v.w};
#pragma unroll
        for (int u = 0; u < 4; u++) {
            int j = j4 + u;
            if (j < L && j > i && vv[u] == 1) js[cnt++] = j;
        }
    }
    int lane = threadIdx.x & 31;
    int scan = cnt;
#pragma unroll
    for (int off = 1; off < 32; off <<= 1) {
        int n = __shfl_up_sync(0xffffffffu, scan, off);
        if (lane >= off) scan += n;
    }
    int total = __shfl_sync(0xffffffffu, scan, 31);
    int base = 0;
    if (lane == 31 && total) base = atomicAdd(&g_ctl.pair_count, total);
    base = __shfl_sync(0xffffffffu, base, 31);
    int pos = base + scan - cnt;
    for (int u = 0; u < cnt; u++)
        if (pos + u < MAX_P) g_pairs[pos + u] = make_int2(i, js[u]);
}

__global__ void pairs_kernel_scalar(const int* __restrict__ m, int L) {
    int i = blockIdx.x;
    int j = blockIdx.y * blockDim.x + threadIdx.x;
    bool pred = (j < L) && (j > i) && (m[(long)i * L + j] == 1);
    unsigned bal = __ballot_sync(0xffffffffu, pred);
    int cnt = __popc(bal);
    int lane = threadIdx.x & 31;
    int base = 0;
    if (lane == 0 && cnt) base = atomicAdd(&g_ctl.pair_count, cnt);
    base = __shfl_sync(0xffffffffu, base, 0);
    if (pred) {
        int r = base + __popc(bal & ((1u << lane) - 1u));
        if (r < MAX_P) g_pairs[r] = make_int2(i, j);
    }
}

/* --------------- main: in-block records + pipelined fma loop -------- */
template<bool FULL>
__global__ void __launch_bounds__(NT_MAIN, 3)
fape_main_kernel(const float* __restrict__ coor, const float* __restrict__ target,
                 const float* __restrict__ rot, const float* __restrict__ trans,
                 int L, int npg, float* __restrict__ out) {
#if __CUDA_ARCH__ >= 900
    cudaGridDependencySynchronize();   /* PDL: wait for prep completion */
#endif
    const int npts = 3 * L;
    const int t = threadIdx.x;
    const int pg     = blockIdx.x % npg;       /* point group */
    const int stripe = blockIdx.x / npg;       /* frame segment index */
    const int pbase  = pg * PTS_PER_GROUP;

    __shared__ ulonglong2 s_fr[TS * 12];
    __shared__ float wsum[NT_MAIN / 32];

    const int F = L + min(g_ctl.pair_count, MAX_P);
    const int seg = (F + NSTRIPE - 1) / NSTRIPE;     /* frames per block segment */
    const int f0 = stripe * seg;
    const int f1 = min(f0 + seg, F);

    /* ---- build first tile's records FIRST (overlaps point LDGs) ---- */
    int tile_base = f0;
    {
        int nf = min(TS, f1 - tile_base);
        if (t < nf) {
            int fidx = tile_base + t;
            float Rp[9], tp[3], Rt[9], tq[3];
            if (fidx < L) {
#pragma unroll
                for (int k = 0; k < 9; k++) Rp[k] = rot[(long)fidx*9 + k];
                tp[0] = trans[fidx*3+0]; tp[1] = trans[fidx*3+1]; tp[2] = trans[fidx*3+2];
                rigid3_dev(target + (long)fidx*9, Rt, tq);
            } else {
                int2 pr = g_pairs[fidx - L];
                int i = pr.x, j = pr.y;
                merge_frames_dev(rot + (long)9*i, trans + (long)3*i,
                                 rot + (long)9*j, trans + (long)3*j, Rp, tp);
                float RA[9], OA[3], RB[9], OB[3];
                rigid3_dev(target + (long)9*i, RA, OA);
                rigid3_dev(target + (long)9*j, RB, OB);
                merge_frames_dev(RA, OA, RB, OB, Rt, tq);
            }
            ulonglong2* o = s_fr + t * 12;
#pragma unroll
            for (int e = 0; e < 3; e++) {
                float c = (Rt[3*e+0]*tq[0] + Rt[3*e+1]*tq[1] + Rt[3*e+2]*tq[2])
                        - (Rp[3*e+0]*tp[0] + Rp[3*e+1]*tp[1] + Rp[3*e+2]*tp[2]);
                ulonglong2 m0, m1, m2, m3;
                m0.x = dupf(Rp[3*e+0]);  m0.y = dupf(Rp[3*e+1]);
                m1.x = dupf(Rp[3*e+2]);  m1.y = dupf(c);
                m2.x = dupf(-Rt[3*e+0]); m2.y = dupf(-Rt[3*e+1]);
                m3.x = dupf(-Rt[3*e+2]); m3.y = 0ull;
                o[4*e+0] = m0; o[4*e+1] = m1; o[4*e+2] = m2; o[4*e+3] = m3;
            }
        }
    }

    /* ---- per-thread points in registers (packed pairs) ---- */
    u64 Px[NSLOT], Py[NSLOT], Pz[NSLOT], Qx[NSLOT], Qy[NSLOT], Qz[NSLOT];
    float M0[NSLOT], M1[NSLOT];
#pragma unroll
    for (int k = 0; k < NSLOT; k++) {
        int n0 = pbase + t + (2*k)   * NT_MAIN;
        int n1 = pbase + t + (2*k+1) * NT_MAIN;
        int a0 = (FULL || n0 < npts) ? n0 : 0;
        int a1 = (FULL || n1 < npts) ? n1 : 0;
        float p0x = coor[3*a0],   p0y = coor[3*a0+1],   p0z = coor[3*a0+2];
        float p1x = coor[3*a1],   p1y = coor[3*a1+1],   p1z = coor[3*a1+2];
        float q0x = target[3*a0], q0y = target[3*a0+1], q0z = target[3*a0+2];
        float q1x = target[3*a1], q1y = target[3*a1+1], q1z = target[3*a1+2];
        PACK2(Px[k], p0x, p1x); PACK2(Py[k], p0y, p1y); PACK2(Pz[k], p0z, p1z);
        PACK2(Qx[k], q0x, q1x); PACK2(Qy[k], q0y, q1y); PACK2(Qz[k], q0z, q1z);
        if (!FULL) {
            M0[k] = (n0 < npts) ? 1.f : 0.f;
            M1[k] = (n1 < npts) ? 1.f : 0.f;
        }
    }

    u64 EPp; PACK2(EPp, EP3, EP3);
    float acc0 = 0.f, acc1 = 0.f;

    auto compute_ss = [&](int lf, u64* ss) {
        const ulonglong2* fr = s_fr + lf * 12;
#pragma unroll
        for (int e = 0; e < 3; e++) {
            ulonglong2 m0 = fr[4*e+0], m1 = fr[4*e+1], m2 = fr[4*e+2], m3 = fr[4*e+3];
            u64 R0 = m0.x, R1 = m0.y, R2 = m1.x, Ce = m1.y;
            u64 S0 = m2.x, S1 = m2.y, S2 = m3.x;
#pragma unroll
            for (int k = 0; k < NSLOT; k++) {
                u64 d;
                FMA2(d, S2, Qz[k], Ce); FMA2(d, S1, Qy[k], d); FMA2(d, S0, Qx[k], d);
                FMA2(d, R2, Pz[k], d);  FMA2(d, R1, Py[k], d); FMA2(d, R0, Px[k], d);
                if (e == 0) { FMA2(ss[k], d, d, EPp); }
                else        { FMA2(ss[k], d, d, ss[k]); }
            }
        }
    };
    auto tail = [&](const u64* ss) {
#pragma unroll
        for (int k = 0; k < NSLOT; k++) {
            float s0, s1; UNPK2(s0, s1, ss[k]);
            s0 = fminf(s0, EPMAX2);  s1 = fminf(s1, EPMAX2);
            float r0, r1;
            asm("sqrt.approx.f32 %0, %1;" : "=f"(r0) : "f"(s0));
            asm("sqrt.approx.f32 %0, %1;" : "=f"(r1) : "f"(s1));
            if (FULL) { acc0 += r0; acc1 += r1; }
            else      { acc0 = fmaf(M0[k], r0, acc0); acc1 = fmaf(M1[k], r1, acc1); }
        }
    };

    while (tile_base < f1) {
        int nf = min(TS, f1 - tile_base);
        __syncthreads();   /* records for this tile ready */

        u64 ssA[NSLOT], ssB[NSLOT];
        compute_ss(0, ssA);
        int lf = 1;
        for (; lf + 1 < nf; lf += 2) {
            compute_ss(lf, ssB);
            tail(ssA);
            compute_ss(lf + 1, ssA);
            tail(ssB);
        }
        if (lf < nf) {
            compute_ss(lf, ssB);
            tail(ssA);
            tail(ssB);
        } else {
            tail(ssA);
        }

        tile_base += TS;
        if (tile_base < f1) {
            __syncthreads();
            int nf2 = min(TS, f1 - tile_base);
            if (t < nf2) {
                int fidx = tile_base + t;
                float Rp[9], tp[3], Rt[9], tq[3];
                if (fidx < L) {
#pragma unroll
                    for (int k = 0; k < 9; k++) Rp[k] = rot[(long)fidx*9 + k];
                    tp[0] = trans[fidx*3+0]; tp[1] = trans[fidx*3+1]; tp[2] = trans[fidx*3+2];
                    rigid3_dev(target + (long)fidx*9, Rt, tq);
                } else {
                    int2 pr = g_pairs[fidx - L];
                    int i = pr.x, j = pr.y;
                    merge_frames_dev(rot + (long)9*i, trans + (long)3*i,
                                     rot + (long)9*j, trans + (long)3*j, Rp, tp);
                    float RA[9], OA[3], RB[9], OB[3];
                    rigid3_dev(target + (long)9*i, RA, OA);
                    rigid3_dev(target + (long)9*j, RB, OB);
                    merge_frames_dev(RA, OA, RB, OB, Rt, tq);
                }
                ulonglong2* o = s_fr + t * 12;
#pragma unroll
                for (int e = 0; e < 3; e++) {
                    float c = (Rt[3*e+0]*tq[0] + Rt[3*e+1]*tq[1] + Rt[3*e+2]*tq[2])
                            - (Rp[3*e+0]*tp[0] + Rp[3*e+1]*tp[1] + Rp[3*e+2]*tp[2]);
                    ulonglong2 m0, m1, m2, m3;
                    m0.x = dupf(Rp[3*e+0]);  m0.y = dupf(Rp[3*e+1]);
                    m1.x = dupf(Rp[3*e+2]);  m1.y = dupf(c);
                    m2.x = dupf(-Rt[3*e+0]); m2.y = dupf(-Rt[3*e+1]);
                    m3.x = dupf(-Rt[3*e+2]); m3.y = 0ull;
                    o[4*e+0] = m0; o[4*e+1] = m1; o[4*e+2] = m2; o[4*e+3] = m3;
                }
            }
        }
    }

    /* block reduction -> one double atomic, last block finalizes + resets */
    float acc = acc0 + acc1;
#pragma unroll
    for (int off = 16; off; off >>= 1)
        acc += __shfl_down_sync(0xffffffffu, acc, off);
    if ((t & 31) == 0) wsum[t >> 5] = acc;
    __syncthreads();
    if (t == 0) {
        float v = 0.f;
#pragma unroll
        for (int w = 0; w < NT_MAIN / 32; w++) v += wsum[w];
        atomicAdd(&g_ctl.sum, (double)v);
        __threadfence();
        int d = atomicAdd(&g_ctl.done, 1);
        if (d == (int)gridDim.x - 1) {
            double s = atomicAdd(&g_ctl.sum, 0.0);
            out[0] = (float)(s / ((double)npts * (double)F));
            /* self-reset for next graph replay */
            g_ctl.pair_count = 0;
            g_ctl.sum = 0.0;
            __threadfence();
            g_ctl.done = 0;
        }
    }
}

/* ------------------------------------------------------------------ */
extern "C" void kernel_launch(void* const* d_in, const int* in_sizes, int n_in,
                              void* d_out, int out_size) {
    const float* coor   = (const float*)d_in[0];
    const float* rot    = (const float*)d_in[1];
    const float* trans  = (const float*)d_in[2];
    const float* target = (const float*)d_in[3];
    const int*   matrix = (const int*)d_in[4];
    int L = in_sizes[0] / 9;
    int npts = 3 * L;

    if ((L & 3) == 0) {
        dim3 pg(L, (L/4 + 255) / 256);
        pairs_kernel_vec4<<<pg, 256>>>(matrix, L);
    } else {
        dim3 pg(L, (L + 255) / 256);
        pairs_kernel_scalar<<<pg, 256>>>(matrix, L);
    }

    int npg = (npts + PTS_PER_GROUP - 1) / PTS_PER_GROUP;
    if (npg < 1) npg = 1;
    dim3 grid(npg * NSTRIPE);
    float* outp = (float*)d_out;

    /* PDL: main's grid launch overlaps prep execution */
    cudaLaunchConfig_t cfg = {};
    cfg.gridDim = grid;
    cfg.blockDim = dim3(NT_MAIN);
    cfg.dynamicSmemBytes = 0;
    cfg.stream = 0;
    cudaLaunchAttribute attrs[1];
    attrs[0].id = cudaLaunchAttributeProgrammaticStreamSerialization;
    attrs[0].val.programmaticStreamSerializationAllowed = 1;
    cfg.attrs = attrs;
    cfg.numAttrs = 1;

    if (npts % PTS_PER_GROUP == 0)
        cudaLaunchKernelEx(&cfg, fape_main_kernel<true>,
                           coor, target, rot, trans, L, npg, outp);
    else
        cudaLaunchKernelEx(&cfg, fape_main_kernel<false>,
                           coor, target, rot, trans, L, npg, outp);
}